// round 1
// baseline (speedup 1.0000x reference)
#include <cuda_runtime.h>
#include <cuda_bf16.h>

#define NS 192
#define NJ (NS / 32)          // 6 chunks of 32 samples per ray
#define FAR_DIST 1e10f
#define EPS_F 1e-10f
#define FULL 0xffffffffu

__global__ __launch_bounds__(256) void render_kernel(
    const float* __restrict__ rgb_raw,   // [B, N, 3]
    const float* __restrict__ density,   // [B, N, 1]
    const float* __restrict__ z_vals,    // [B, N]
    const float* __restrict__ dir,       // [B, 3]
    float* __restrict__ out,             // rgb[B*3] | weights[B*N] | depth[B] | acc[B] | disp[B]
    int nrays)
{
    const int warp_global = (blockIdx.x * blockDim.x + threadIdx.x) >> 5;
    const int lane = threadIdx.x & 31;
    if (warp_global >= nrays) return;
    const int b = warp_global;

    // ray direction norm (broadcast read, L1/L2 hit for 31/32 lanes)
    const float dx = dir[b * 3 + 0];
    const float dy = dir[b * 3 + 1];
    const float dz = dir[b * 3 + 2];
    const float dnorm = sqrtf(dx * dx + dy * dy + dz * dz);

    const float* __restrict__ zb = z_vals  + (size_t)b * NS;
    const float* __restrict__ db = density + (size_t)b * NS;
    const float* __restrict__ cb = rgb_raw + (size_t)b * NS * 3;

    // preload z and density, coalesced: sample n = j*32 + lane
    float z[NJ], dens[NJ];
#pragma unroll
    for (int j = 0; j < NJ; j++) {
        z[j]    = zb[j * 32 + lane];
        dens[j] = db[j * 32 + lane];
    }

    float* __restrict__ w_out = out + (size_t)nrays * 3 + (size_t)b * NS;

    float rs0 = 0.f, rs1 = 0.f, rs2 = 0.f;   // rgb accumulators
    float dsum = 0.f, asum = 0.f;            // depth, acc
    float run = 1.f;                          // product of t over all previous chunks

#pragma unroll
    for (int j = 0; j < NJ; j++) {
        // dist = z[n+1] - z[n]; last sample gets FAR_DIST
        float zn  = __shfl_down_sync(FULL, z[j], 1);
        float znb = (j + 1 < NJ) ? __shfl_sync(FULL, z[j + 1], 0) : 0.f;
        if (lane == 31) zn = znb;
        float dist = zn - z[j];
        if (j == NJ - 1 && lane == 31) dist = FAR_DIST;
        dist *= dnorm;

        const float sd    = fmaxf(dens[j], 0.f);
        const float t_exp = __expf(-sd * dist);      // exp(-relu(d)*dist)
        const float alpha = 1.f - t_exp;
        float t = t_exp + EPS_F;                     // 1 - alpha + EPS

        // inclusive prefix product over lanes (Hillis–Steele)
        float incl = t;
#pragma unroll
        for (int off = 1; off < 32; off <<= 1) {
            float v = __shfl_up_sync(FULL, incl, off);
            if (lane >= off) incl *= v;
        }
        // exclusive = shifted inclusive
        float excl = __shfl_up_sync(FULL, incl, 1);
        if (lane == 0) excl = 1.f;
        const float total = __shfl_sync(FULL, incl, 31);

        const float trans = run * excl;
        run *= total;

        const float w = alpha * trans;
        const int n = j * 32 + lane;
        w_out[n] = w;

        // sigmoid(rgb_raw) weighted accumulation
        const float r0 = cb[n * 3 + 0];
        const float r1 = cb[n * 3 + 1];
        const float r2 = cb[n * 3 + 2];
        rs0 += w * (1.f / (1.f + __expf(-r0)));
        rs1 += w * (1.f / (1.f + __expf(-r1)));
        rs2 += w * (1.f / (1.f + __expf(-r2)));
        dsum += w * z[j];
        asum += w;
    }

    // warp reductions (5 values)
#pragma unroll
    for (int off = 16; off >= 1; off >>= 1) {
        rs0  += __shfl_down_sync(FULL, rs0, off);
        rs1  += __shfl_down_sync(FULL, rs1, off);
        rs2  += __shfl_down_sync(FULL, rs2, off);
        dsum += __shfl_down_sync(FULL, dsum, off);
        asum += __shfl_down_sync(FULL, asum, off);
    }

    if (lane == 0) {
        out[b * 3 + 0] = rs0;
        out[b * 3 + 1] = rs1;
        out[b * 3 + 2] = rs2;
        float* depth_out = out + (size_t)nrays * 3 + (size_t)nrays * NS;
        float* acc_out   = depth_out + nrays;
        float* disp_out  = acc_out + nrays;
        depth_out[b] = dsum;
        acc_out[b]   = asum;
        disp_out[b]  = 1.f / fmaxf(EPS_F, dsum / asum);
    }
}

extern "C" void kernel_launch(void* const* d_in, const int* in_sizes, int n_in,
                              void* d_out, int out_size)
{
    const float* rgb_raw = (const float*)d_in[0];
    const float* density = (const float*)d_in[1];
    const float* z_vals  = (const float*)d_in[2];
    const float* dir     = (const float*)d_in[3];
    float* out = (float*)d_out;

    const int nrays = in_sizes[3] / 3;   // dir is [B, 3]

    // one warp per ray, 8 warps per block
    const int threads = 256;
    const int warps_per_block = threads / 32;
    const int blocks = (nrays + warps_per_block - 1) / warps_per_block;
    render_kernel<<<blocks, threads>>>(rgb_raw, density, z_vals, dir, out, nrays);
}

// round 3
// speedup vs baseline: 1.2495x; 1.2495x over previous
#include <cuda_runtime.h>
#include <cuda_bf16.h>

#define NS 192
#define SEG 6                 // samples per lane (32*6 = 192)
#define FAR_DIST 1e10f
#define EPS_F 1e-10f
#define FULL 0xffffffffu
#define WARPS_PER_BLOCK 8
#define THREADS (WARPS_PER_BLOCK * 32)

// per-warp smem floats: z[192] | dens[192]->weights | rgb[576]
#define W_FLOATS 960

__global__ __launch_bounds__(THREADS) void render_kernel(
    const float* __restrict__ rgb_raw,   // [B, N, 3]
    const float* __restrict__ density,   // [B, N, 1]
    const float* __restrict__ z_vals,    // [B, N]
    const float* __restrict__ dir,       // [B, 3]
    float* __restrict__ out,             // rgb[B*3] | weights[B*N] | depth[B] | acc[B] | disp[B]
    int nrays)
{
    __shared__ float sm[WARPS_PER_BLOCK * W_FLOATS];

    const int warp_in_blk = threadIdx.x >> 5;
    const int lane = threadIdx.x & 31;
    const int b = blockIdx.x * WARPS_PER_BLOCK + warp_in_blk;
    if (b >= nrays) return;

    float* __restrict__ sz = sm + warp_in_blk * W_FLOATS;        // [0,192)
    float* __restrict__ sd = sz + NS;                            // [192,384) dens -> weights
    float* __restrict__ sr = sd + NS;                            // [384,960) rgb

    // ---- stage inputs with coalesced float4 loads ----
    {
        const float4* __restrict__ z4 = (const float4*)(z_vals  + (size_t)b * NS);      // 48
        const float4* __restrict__ d4 = (const float4*)(density + (size_t)b * NS);      // 48
        const float4* __restrict__ r4 = (const float4*)(rgb_raw + (size_t)b * NS * 3);  // 144
        float4* __restrict__ sz4 = (float4*)sz;
        float4* __restrict__ sd4 = (float4*)sd;
        float4* __restrict__ sr4 = (float4*)sr;
        sz4[lane] = z4[lane];
        sd4[lane] = d4[lane];
        if (lane < 16) { sz4[32 + lane] = z4[32 + lane]; sd4[32 + lane] = d4[32 + lane]; }
#pragma unroll
        for (int i = 0; i < 4; i++) sr4[i * 32 + lane] = r4[i * 32 + lane];
        if (lane < 16) sr4[128 + lane] = r4[128 + lane];
    }

    // ray direction norm (broadcast)
    const float dx = dir[b * 3 + 0];
    const float dy = dir[b * 3 + 1];
    const float dz = dir[b * 3 + 2];
    const float dnorm = sqrtf(dx * dx + dy * dy + dz * dz);

    __syncwarp();

    // ---- phase 1: per-lane segment of SEG consecutive samples ----
    const int s0 = lane * SEG;
    float e[SEG];           // exp(-relu(dens)*dist) per sample
    float p = 1.f;          // product of (e + EPS) over this lane's segment
    float zc = sz[s0];
#pragma unroll
    for (int i = 0; i < SEG; i++) {
        const bool last = (s0 + i == NS - 1);
        const float zn = last ? 0.f : sz[s0 + i + 1];
        const float dist = last ? (FAR_DIST * dnorm) : ((zn - zc) * dnorm);
        zc = zn;
        const float sdv = fmaxf(sd[s0 + i], 0.f);
        e[i] = __expf(-sdv * dist);
        p *= (e[i] + EPS_F);
    }

    // ---- one exclusive scan over the 32 lane products ----
    float incl = p;
#pragma unroll
    for (int off = 1; off < 32; off <<= 1) {
        const float v = __shfl_up_sync(FULL, incl, off);
        if (lane >= off) incl *= v;
    }
    float trans = __shfl_up_sync(FULL, incl, 1);
    if (lane == 0) trans = 1.f;

    // ---- phase 2: weights + accumulations (sequential within segment) ----
    float rs0 = 0.f, rs1 = 0.f, rs2 = 0.f, dsum = 0.f, asum = 0.f;
    const float* __restrict__ rp = sr + s0 * 3;   // lane-contiguous 18 floats
#pragma unroll
    for (int i = 0; i < SEG; i++) {
        const float alpha = 1.f - e[i];
        const float w = alpha * trans;
        trans *= (e[i] + EPS_F);
        sd[s0 + i] = w;                         // reuse dens smem for weights
        const float zi = sz[s0 + i];
        const float r0 = rp[i * 3 + 0];
        const float r1 = rp[i * 3 + 1];
        const float r2 = rp[i * 3 + 2];
        rs0 = fmaf(w, __fdividef(1.f, 1.f + __expf(-r0)), rs0);
        rs1 = fmaf(w, __fdividef(1.f, 1.f + __expf(-r1)), rs1);
        rs2 = fmaf(w, __fdividef(1.f, 1.f + __expf(-r2)), rs2);
        dsum = fmaf(w, zi, dsum);
        asum += w;
    }

    __syncwarp();

    // ---- coalesced float4 store of weights ----
    {
        float4* __restrict__ w4 = (float4*)(out + (size_t)nrays * 3 + (size_t)b * NS);
        const float4* __restrict__ sd4 = (const float4*)sd;
        w4[lane] = sd4[lane];
        if (lane < 16) w4[32 + lane] = sd4[32 + lane];
    }

    // ---- warp reductions (5 values) ----
#pragma unroll
    for (int off = 16; off >= 1; off >>= 1) {
        rs0  += __shfl_down_sync(FULL, rs0, off);
        rs1  += __shfl_down_sync(FULL, rs1, off);
        rs2  += __shfl_down_sync(FULL, rs2, off);
        dsum += __shfl_down_sync(FULL, dsum, off);
        asum += __shfl_down_sync(FULL, asum, off);
    }

    if (lane == 0) {
        out[b * 3 + 0] = rs0;
        out[b * 3 + 1] = rs1;
        out[b * 3 + 2] = rs2;
        float* depth_out = out + (size_t)nrays * 3 + (size_t)nrays * NS;
        float* acc_out   = depth_out + nrays;
        float* disp_out  = acc_out + nrays;
        depth_out[b] = dsum;
        acc_out[b]   = asum;
        disp_out[b]  = 1.f / fmaxf(EPS_F, dsum / asum);
    }
}

extern "C" void kernel_launch(void* const* d_in, const int* in_sizes, int n_in,
                              void* d_out, int out_size)
{
    const float* rgb_raw = (const float*)d_in[0];
    const float* density = (const float*)d_in[1];
    const float* z_vals  = (const float*)d_in[2];
    const float* dir     = (const float*)d_in[3];
    float* out = (float*)d_out;

    const int nrays = in_sizes[3] / 3;   // dir is [B, 3]

    const int blocks = (nrays + WARPS_PER_BLOCK - 1) / WARPS_PER_BLOCK;
    render_kernel<<<blocks, THREADS>>>(rgb_raw, density, z_vals, dir, out, nrays);
}